// round 1
// baseline (speedup 1.0000x reference)
#include <cuda_runtime.h>

#define NN 100000
#define NE 300000
#define NB 1024

// ---------------- device scratch (static: no runtime allocation) ----------------
__device__ float g_x1[NN * 64];          // layer0 output, all nodes   (25.6 MB)
__device__ float g_x2[NN * 128];         // layer1 output, N1 nodes    (51.2 MB)
__device__ float g_agg[NN * 128];        // shared aggregation buffer  (51.2 MB)
__device__ unsigned char g_maskB[NN];
__device__ unsigned char g_maskN1[NN];
__device__ int g_list[NN];
__device__ int g_cnt;
__device__ float g_pool[256];
__device__ float g_bsum[3];

// ---------------- setup / masks ----------------
__global__ void k_init() {
    int i = blockIdx.x * 256 + threadIdx.x;
    if (i < NN) { g_maskB[i] = 0; g_maskN1[i] = 0; }
    if (i < 256) g_pool[i] = 0.f;
    if (i < 3) g_bsum[i] = 0.f;
    if (i == 0) g_cnt = 0;
}

__global__ void k_markB(const int* __restrict__ bidx) {
    int j = blockIdx.x * 256 + threadIdx.x;
    if (j < NB) { int n = bidx[j]; g_maskB[n] = 1; g_maskN1[n] = 1; }
}

__global__ void k_markN1(const int* __restrict__ edges) {
    int e = blockIdx.x * 256 + threadIdx.x;
    if (e >= NE) return;
    int s = edges[2 * e], d = edges[2 * e + 1];
    if (g_maskB[d]) g_maskN1[s] = 1;
    if (g_maskB[s]) g_maskN1[d] = 1;
}

__global__ void k_compact() {
    int i = blockIdx.x * 256 + threadIdx.x;
    if (i < NN && g_maskN1[i]) g_list[atomicAdd(&g_cnt, 1)] = i;
}

__global__ void k_zero4(int n4) {
    int i = blockIdx.x * 256 + threadIdx.x;
    if (i < n4) ((float4*)g_agg)[i] = make_float4(0.f, 0.f, 0.f, 0.f);
}

// ---------------- layer 0 (cin=3, cout=64): all nodes ----------------
__global__ void k_edge0(const float* __restrict__ vs, const int* __restrict__ edges) {
    int e = blockIdx.x * 256 + threadIdx.x;
    if (e >= NE) return;
    int s = edges[2 * e], d = edges[2 * e + 1];
    float sx = vs[3 * s], sy = vs[3 * s + 1], sz = vs[3 * s + 2];
    float dx = vs[3 * d], dy = vs[3 * d + 1], dz = vs[3 * d + 2];
    atomicAdd(&g_agg[3 * d + 0], sx);
    atomicAdd(&g_agg[3 * d + 1], sy);
    atomicAdd(&g_agg[3 * d + 2], sz);
    atomicAdd(&g_agg[3 * s + 0], dx);
    atomicAdd(&g_agg[3 * s + 1], dy);
    atomicAdd(&g_agg[3 * s + 2], dz);
}

__global__ void k_node0(const float* __restrict__ vs,
                        const float* __restrict__ Ws, const float* __restrict__ Wn,
                        const float* __restrict__ b) {
    int t = blockIdx.x * 256 + threadIdx.x;
    if (t >= NN * 64) return;
    int node = t >> 6, c = t & 63;
    float acc = b[c];
#pragma unroll
    for (int k = 0; k < 3; k++)
        acc += vs[3 * node + k] * Ws[k * 64 + c] + g_agg[3 * node + k] * Wn[k * 64 + c];
    g_x1[t] = fmaxf(acc, 0.f);   // t == node*64 + c
}

// ---------------- layer 1 (cin=64, cout=128): only N1 nodes ----------------
__global__ void k_edge1(const int* __restrict__ edges) {
    int gid = blockIdx.x * 256 + threadIdx.x;
    int e = gid >> 4;
    if (e >= NE) return;
    int c = (gid & 15) * 4;
    int s = edges[2 * e], d = edges[2 * e + 1];
    if (g_maskN1[d]) {
        float4 v = *(const float4*)&g_x1[s * 64 + c];
        atomicAdd(&g_agg[d * 64 + c + 0], v.x);
        atomicAdd(&g_agg[d * 64 + c + 1], v.y);
        atomicAdd(&g_agg[d * 64 + c + 2], v.z);
        atomicAdd(&g_agg[d * 64 + c + 3], v.w);
    }
    if (g_maskN1[s]) {
        float4 v = *(const float4*)&g_x1[d * 64 + c];
        atomicAdd(&g_agg[s * 64 + c + 0], v.x);
        atomicAdd(&g_agg[s * 64 + c + 1], v.y);
        atomicAdd(&g_agg[s * 64 + c + 2], v.z);
        atomicAdd(&g_agg[s * 64 + c + 3], v.w);
    }
}

__global__ void k_node1(const float* __restrict__ Ws, const float* __restrict__ Wn,
                        const float* __restrict__ b) {
    extern __shared__ float sm[];
    float* sWs = sm;            // 64*128 = 8192 floats
    float* sWn = sm + 8192;     // 8192 floats
    __shared__ float xs[64], as[64];
    int tid = threadIdx.x;
    for (int i = tid; i < 8192; i += 128) { sWs[i] = Ws[i]; sWn[i] = Wn[i]; }
    float bc = b[tid];
    __syncthreads();
    int cnt = g_cnt;
    for (int idx = blockIdx.x; idx < cnt; idx += gridDim.x) {
        int node = g_list[idx];
        if (tid < 64) {
            xs[tid] = g_x1[node * 64 + tid];
            as[tid] = g_agg[node * 64 + tid];
        }
        __syncthreads();
        float acc = bc;
#pragma unroll 16
        for (int k = 0; k < 64; k++)
            acc += xs[k] * sWs[k * 128 + tid] + as[k] * sWn[k * 128 + tid];
        g_x2[node * 128 + tid] = fmaxf(acc, 0.f);
        __syncthreads();
    }
}

// ---------------- layer 2 (cin=128, cout=256): only boundary nodes ----------------
__global__ void k_edge2(const int* __restrict__ edges) {
    int gid = blockIdx.x * 256 + threadIdx.x;
    int e = gid >> 5;
    if (e >= NE) return;
    int c = (gid & 31) * 4;
    int s = edges[2 * e], d = edges[2 * e + 1];
    if (g_maskB[d]) {
        float4 v = *(const float4*)&g_x2[s * 128 + c];
        atomicAdd(&g_agg[d * 128 + c + 0], v.x);
        atomicAdd(&g_agg[d * 128 + c + 1], v.y);
        atomicAdd(&g_agg[d * 128 + c + 2], v.z);
        atomicAdd(&g_agg[d * 128 + c + 3], v.w);
    }
    if (g_maskB[s]) {
        float4 v = *(const float4*)&g_x2[d * 128 + c];
        atomicAdd(&g_agg[s * 128 + c + 0], v.x);
        atomicAdd(&g_agg[s * 128 + c + 1], v.y);
        atomicAdd(&g_agg[s * 128 + c + 2], v.z);
        atomicAdd(&g_agg[s * 128 + c + 3], v.w);
    }
}

__global__ void k_bsum(const float* __restrict__ vs, const int* __restrict__ bidx) {
    int tid = threadIdx.x;
    float s0 = 0.f, s1 = 0.f, s2 = 0.f;
    for (int j = tid; j < NB; j += 256) {
        int n = bidx[j];
        s0 += vs[3 * n];
        s1 += vs[3 * n + 1];
        s2 += vs[3 * n + 2];
    }
    atomicAdd(&g_bsum[0], s0);
    atomicAdd(&g_bsum[1], s1);
    atomicAdd(&g_bsum[2], s2);
}

// layer-2 conv fused with boundary pooling: each block handles 8 boundary
// entries, W staged in smem in two cout-chunks of 128, block-local pool
// partials reduced then one atomicAdd per (block, channel).
__global__ void k_node2(const int* __restrict__ bidx,
                        const float* __restrict__ Ws, const float* __restrict__ Wn,
                        const float* __restrict__ b) {
    extern __shared__ float sm[];
    float* sWs = sm;            // 128*128 = 16384 floats
    float* sWn = sm + 16384;    // 16384 floats
    __shared__ float xs[128], as[128];
    int tid = threadIdx.x;
    for (int h = 0; h < 2; h++) {
        __syncthreads();
        for (int i = tid; i < 16384; i += 128) {
            int k = i >> 7, c = i & 127;
            sWs[i] = Ws[k * 256 + h * 128 + c];
            sWn[i] = Wn[k * 256 + h * 128 + c];
        }
        float bb = b[h * 128 + tid];
        __syncthreads();
        float pacc = 0.f;
        for (int e = 0; e < 8; e++) {
            int node = bidx[blockIdx.x * 8 + e];
            xs[tid] = g_x2[node * 128 + tid];
            as[tid] = g_agg[node * 128 + tid];
            __syncthreads();
            float acc = bb;
#pragma unroll 16
            for (int k = 0; k < 128; k++)
                acc += xs[k] * sWs[k * 128 + tid] + as[k] * sWn[k * 128 + tid];
            pacc += fmaxf(acc, 0.f);
            __syncthreads();
        }
        atomicAdd(&g_pool[h * 128 + tid], pacc);
    }
}

// ---------------- dense head ----------------
__global__ void k_final(const float* __restrict__ Wd, const float* __restrict__ bd,
                        const float* __restrict__ Wo, const float* __restrict__ bo,
                        float* __restrict__ out) {
    __shared__ float sp[256], sh[256];
    int tid = threadIdx.x;
    sp[tid] = g_pool[tid] * (1.f / NB);
    __syncthreads();
    float acc = bd[tid];
#pragma unroll 8
    for (int k = 0; k < 256; k++) acc += sp[k] * Wd[k * 256 + tid];
    sh[tid] = fmaxf(acc, 0.f);
    __syncthreads();
    if (tid < 12) {
        float o = bo[tid];
        for (int k = 0; k < 256; k++) o += sh[k] * Wo[k * 12 + tid];
        out[tid] = o + g_bsum[tid % 3] * (1.f / NB);
    }
}

// ---------------- host launch ----------------
extern "C" void kernel_launch(void* const* d_in, const int* in_sizes, int n_in,
                              void* d_out, int out_size) {
    const float* vs    = (const float*)d_in[0];
    const int*   edges = (const int*)d_in[1];
    const int*   bidx  = (const int*)d_in[2];
    int wb = n_in - 13;   // 13 trailing weight tensors; robust to n_verts scalar presence
    const float* Ws0 = (const float*)d_in[wb + 0];
    const float* Wn0 = (const float*)d_in[wb + 1];
    const float* b0  = (const float*)d_in[wb + 2];
    const float* Ws1 = (const float*)d_in[wb + 3];
    const float* Wn1 = (const float*)d_in[wb + 4];
    const float* b1  = (const float*)d_in[wb + 5];
    const float* Ws2 = (const float*)d_in[wb + 6];
    const float* Wn2 = (const float*)d_in[wb + 7];
    const float* b2  = (const float*)d_in[wb + 8];
    const float* Wd  = (const float*)d_in[wb + 9];
    const float* bd  = (const float*)d_in[wb + 10];
    const float* Wo  = (const float*)d_in[wb + 11];
    const float* bo  = (const float*)d_in[wb + 12];
    float* out = (float*)d_out;

    cudaFuncSetAttribute(k_node1, cudaFuncAttributeMaxDynamicSharedMemorySize, 65536);
    cudaFuncSetAttribute(k_node2, cudaFuncAttributeMaxDynamicSharedMemorySize, 131072);

    k_init<<<(NN + 255) / 256, 256>>>();
    k_markB<<<(NB + 255) / 256, 256>>>(bidx);
    k_markN1<<<(NE + 255) / 256, 256>>>(edges);
    k_compact<<<(NN + 255) / 256, 256>>>();

    // layer 0 (all nodes)
    k_zero4<<<(NN * 3 / 4 + 255) / 256, 256>>>(NN * 3 / 4);
    k_edge0<<<(NE + 255) / 256, 256>>>(vs, edges);
    k_node0<<<(NN * 64) / 256, 256>>>(vs, Ws0, Wn0, b0);

    // layer 1 (N1 nodes only)
    k_zero4<<<(NN * 16 + 255) / 256, 256>>>(NN * 16);
    k_edge1<<<(NE * 16) / 256, 256>>>(edges);
    k_node1<<<512, 128, 65536>>>(Ws1, Wn1, b1);

    // layer 2 (boundary nodes only) + pooling
    k_zero4<<<(NN * 32 + 255) / 256, 256>>>(NN * 32);
    k_edge2<<<(NE * 32) / 256, 256>>>(edges);
    k_bsum<<<1, 256>>>(vs, bidx);
    k_node2<<<128, 128, 131072>>>(bidx, Ws2, Wn2, b2);

    // dense head
    k_final<<<1, 256>>>(Wd, bd, Wo, bo, out);
}

// round 3
// speedup vs baseline: 1.4500x; 1.4500x over previous
#include <cuda_runtime.h>

#define NN 100000
#define NE 300000
#define NB 1024
#define GSB 592           // grid blocks for dynamic-work kernels

// ---------------- device scratch (static) ----------------
__device__ float g_x1[NN * 64];           // layer0 out, dense rows (written only at N2)
__device__ float g_x2c[NN * 128];         // layer1 out, compact by slot1
__device__ float g_agg0[NN * 3];          // position aggregation (dense, small)
__device__ float g_agg1[NN * 64];         // layer1 agg, compact by slot1 (only [0,cnt1) used)
__device__ float g_agg2[NB * 128];        // layer2 agg, compact by slot2
__device__ unsigned char g_maskB[NN];
__device__ unsigned char g_maskN1[NN];
__device__ unsigned char g_maskN2[NN];
__device__ int g_slot1[NN];
__device__ int g_slot2[NN];
__device__ int g_list1[NN];               // slot1 -> node
__device__ int g_list2[NN];               // N2 node list
__device__ int2 g_e1[NE];                 // active layer1 edges (packed)
__device__ int2 g_e2[NE];                 // active layer2 edges (packed)
__device__ int g_cnt1, g_cnt2, g_cntE1, g_cntE2;
__device__ float g_pool[256];
__device__ float g_bsum[3];

// ---------------- init: zero masks, agg0, agg2, counters ----------------
__global__ void k_init() {
    int i = blockIdx.x * 256 + threadIdx.x;
    if (i < NN) {
        g_maskB[i] = 0; g_maskN1[i] = 0; g_maskN2[i] = 0;
        g_agg0[3 * i + 0] = 0.f; g_agg0[3 * i + 1] = 0.f; g_agg0[3 * i + 2] = 0.f;
    }
    if (i < NB * 128) g_agg2[i] = 0.f;
    if (i < 256) g_pool[i] = 0.f;
    if (i < 3) g_bsum[i] = 0.f;
    if (i == 0) { g_cnt1 = 0; g_cnt2 = 0; g_cntE1 = 0; g_cntE2 = 0; }
}

// ---------------- mark boundary + boundary mean of vs ----------------
__global__ void k_markB(const float* __restrict__ vs, const int* __restrict__ bidx) {
    int tid = threadIdx.x;
    float s0 = 0.f, s1 = 0.f, s2 = 0.f;
    for (int j = tid; j < NB; j += 256) {
        int n = bidx[j];
        g_maskB[n] = 1; g_maskN1[n] = 1; g_slot2[n] = j;
        s0 += vs[3 * n]; s1 += vs[3 * n + 1]; s2 += vs[3 * n + 2];
    }
    atomicAdd(&g_bsum[0], s0);
    atomicAdd(&g_bsum[1], s1);
    atomicAdd(&g_bsum[2], s2);
}

// ---------------- pass 1: layer0 position agg + mark N1 + emit layer2 edges ----------------
__global__ void k_pass1(const float* __restrict__ vs, const int* __restrict__ edges) {
    int e = blockIdx.x * 256 + threadIdx.x;
    if (e >= NE) return;
    int s = edges[2 * e], d = edges[2 * e + 1];
    float sx = vs[3 * s], sy = vs[3 * s + 1], sz = vs[3 * s + 2];
    float dx = vs[3 * d], dy = vs[3 * d + 1], dz = vs[3 * d + 2];
    atomicAdd(&g_agg0[3 * d + 0], sx);
    atomicAdd(&g_agg0[3 * d + 1], sy);
    atomicAdd(&g_agg0[3 * d + 2], sz);
    atomicAdd(&g_agg0[3 * s + 0], dx);
    atomicAdd(&g_agg0[3 * s + 1], dy);
    atomicAdd(&g_agg0[3 * s + 2], dz);
    int bs = g_maskB[s], bd = g_maskB[d];
    if (bs | bd) {
        if (bd) g_maskN1[s] = 1;
        if (bs) g_maskN1[d] = 1;
        int p = atomicAdd(&g_cntE2, 1);
        g_e2[p] = make_int2(s | (bs << 30), d | (bd << 30));
    }
}

// ---------------- pass 2: mark N2 + emit layer1 edges ----------------
__global__ void k_pass2(const int* __restrict__ edges) {
    int e = blockIdx.x * 256 + threadIdx.x;
    if (e >= NE) return;
    int s = edges[2 * e], d = edges[2 * e + 1];
    int as = g_maskN1[s], ad = g_maskN1[d];
    if (as | ad) {
        if (ad) g_maskN2[s] = 1;     // need x1[s]
        if (as) g_maskN2[d] = 1;     // need x1[d]
        int p = atomicAdd(&g_cntE1, 1);
        g_e1[p] = make_int2(s | (as << 30), d | (ad << 30));
    }
}

// ---------------- compaction ----------------
__global__ void k_compact() {
    int i = blockIdx.x * 256 + threadIdx.x;
    if (i >= NN) return;
    int n1 = g_maskN1[i];
    if (n1) { int p = atomicAdd(&g_cnt1, 1); g_slot1[i] = p; g_list1[p] = i; }
    if (n1 | g_maskN2[i]) { int p = atomicAdd(&g_cnt2, 1); g_list2[p] = i; }
}

// ---------------- zero compact agg1 ----------------
__global__ void k_zero_agg1() {
    int tot = g_cnt1 * 16;                 // float4 count
    int stride = gridDim.x * blockDim.x;
    float4 z = make_float4(0.f, 0.f, 0.f, 0.f);
    for (int i = blockIdx.x * blockDim.x + threadIdx.x; i < tot; i += stride)
        ((float4*)g_agg1)[i] = z;
}

// ---------------- layer 0 node update (N2 nodes only) ----------------
__global__ void k_node0(const float* __restrict__ vs,
                        const float* __restrict__ Ws, const float* __restrict__ Wn,
                        const float* __restrict__ b) {
    int tot = g_cnt2 << 6;
    int stride = gridDim.x * blockDim.x;
    for (int t = blockIdx.x * blockDim.x + threadIdx.x; t < tot; t += stride) {
        int ni = t >> 6, c = t & 63;
        int node = g_list2[ni];
        float acc = b[c];
#pragma unroll
        for (int k = 0; k < 3; k++)
            acc += vs[3 * node + k] * Ws[k * 64 + c] + g_agg0[3 * node + k] * Wn[k * 64 + c];
        g_x1[node * 64 + c] = fmaxf(acc, 0.f);
    }
}

// ---------------- layer 1 edge aggregation (active edges only) ----------------
__global__ void k_edge1() {
    int tot = g_cntE1 << 4;
    int stride = gridDim.x * blockDim.x;
    for (int t = blockIdx.x * blockDim.x + threadIdx.x; t < tot; t += stride) {
        int ei = t >> 4, c = (t & 15) * 4;
        int2 en = g_e1[ei];
        int s = en.x & 0x3FFFFFFF, sa = (unsigned)en.x >> 30;
        int d = en.y & 0x3FFFFFFF, da = (unsigned)en.y >> 30;
        if (da) {                              // agg1[d] += x1[s]
            float4 v = *(const float4*)&g_x1[s * 64 + c];
            float* a = &g_agg1[g_slot1[d] * 64 + c];
            atomicAdd(a + 0, v.x); atomicAdd(a + 1, v.y);
            atomicAdd(a + 2, v.z); atomicAdd(a + 3, v.w);
        }
        if (sa) {                              // agg1[s] += x1[d]
            float4 v = *(const float4*)&g_x1[d * 64 + c];
            float* a = &g_agg1[g_slot1[s] * 64 + c];
            atomicAdd(a + 0, v.x); atomicAdd(a + 1, v.y);
            atomicAdd(a + 2, v.z); atomicAdd(a + 3, v.w);
        }
    }
}

// ---------------- layer 1 node update (N1 slots) ----------------
__global__ void k_node1(const float* __restrict__ Ws, const float* __restrict__ Wn,
                        const float* __restrict__ b) {
    extern __shared__ float sm[];
    float* sWs = sm;            // 64*128
    float* sWn = sm + 8192;
    __shared__ float xs[64], as[64];
    int tid = threadIdx.x;
    for (int i = tid; i < 8192; i += 128) { sWs[i] = Ws[i]; sWn[i] = Wn[i]; }
    float bc = b[tid];
    __syncthreads();
    int cnt = g_cnt1;
    for (int slot = blockIdx.x; slot < cnt; slot += gridDim.x) {
        int node = g_list1[slot];
        if (tid < 64) {
            xs[tid] = g_x1[node * 64 + tid];
            as[tid] = g_agg1[slot * 64 + tid];
        }
        __syncthreads();
        float acc = bc;
#pragma unroll 16
        for (int k = 0; k < 64; k++)
            acc += xs[k] * sWs[k * 128 + tid] + as[k] * sWn[k * 128 + tid];
        g_x2c[slot * 128 + tid] = fmaxf(acc, 0.f);
        __syncthreads();
    }
}

// ---------------- layer 2 edge aggregation (active edges only) ----------------
__global__ void k_edge2() {
    int tot = g_cntE2 << 5;
    int stride = gridDim.x * blockDim.x;
    for (int t = blockIdx.x * blockDim.x + threadIdx.x; t < tot; t += stride) {
        int ei = t >> 5, c = (t & 31) * 4;
        int2 en = g_e2[ei];
        int s = en.x & 0x3FFFFFFF, bs = (unsigned)en.x >> 30;
        int d = en.y & 0x3FFFFFFF, bd = (unsigned)en.y >> 30;
        if (bd) {                              // agg2[d] += x2[s],  s in N1
            float4 v = *(const float4*)&g_x2c[g_slot1[s] * 128 + c];
            float* a = &g_agg2[g_slot2[d] * 128 + c];
            atomicAdd(a + 0, v.x); atomicAdd(a + 1, v.y);
            atomicAdd(a + 2, v.z); atomicAdd(a + 3, v.w);
        }
        if (bs) {
            float4 v = *(const float4*)&g_x2c[g_slot1[d] * 128 + c];
            float* a = &g_agg2[g_slot2[s] * 128 + c];
            atomicAdd(a + 0, v.x); atomicAdd(a + 1, v.y);
            atomicAdd(a + 2, v.z); atomicAdd(a + 3, v.w);
        }
    }
}

// ---------------- layer 2 node update + boundary pooling ----------------
// 128 blocks: block = (group g in [0,64)) x (cout half h in {0,1}); 16 entries/block
__global__ void k_node2(const int* __restrict__ bidx,
                        const float* __restrict__ Ws, const float* __restrict__ Wn,
                        const float* __restrict__ b) {
    extern __shared__ float sm[];
    float* sWs = sm;            // 128*128 for this half
    float* sWn = sm + 16384;
    __shared__ float xs[128], as[128];
    int tid = threadIdx.x;
    int h = blockIdx.x & 1, g = blockIdx.x >> 1;
    for (int i = tid; i < 16384; i += 128) {
        int k = i >> 7, c = i & 127;
        sWs[i] = Ws[k * 256 + h * 128 + c];
        sWn[i] = Wn[k * 256 + h * 128 + c];
    }
    float bb = b[h * 128 + tid];
    __syncthreads();
    float pacc = 0.f;
    for (int e = 0; e < 16; e++) {
        int node = bidx[g * 16 + e];
        xs[tid] = g_x2c[g_slot1[node] * 128 + tid];
        as[tid] = g_agg2[g_slot2[node] * 128 + tid];
        __syncthreads();
        float acc = bb;
#pragma unroll 16
        for (int k = 0; k < 128; k++)
            acc += xs[k] * sWs[k * 128 + tid] + as[k] * sWn[k * 128 + tid];
        pacc += fmaxf(acc, 0.f);
        __syncthreads();
    }
    atomicAdd(&g_pool[h * 128 + tid], pacc);
}

// ---------------- dense head ----------------
__global__ void k_final(const float* __restrict__ Wd, const float* __restrict__ bd,
                        const float* __restrict__ Wo, const float* __restrict__ bo,
                        float* __restrict__ out) {
    __shared__ float sp[256], sh[256];
    int tid = threadIdx.x;
    sp[tid] = g_pool[tid] * (1.f / NB);
    __syncthreads();
    float acc = bd[tid];
#pragma unroll 8
    for (int k = 0; k < 256; k++) acc += sp[k] * Wd[k * 256 + tid];
    sh[tid] = fmaxf(acc, 0.f);
    __syncthreads();
    if (tid < 12) {
        float o = bo[tid];
        for (int k = 0; k < 256; k++) o += sh[k] * Wo[k * 12 + tid];
        out[tid] = o + g_bsum[tid % 3] * (1.f / NB);
    }
}

// ---------------- host launch ----------------
extern "C" void kernel_launch(void* const* d_in, const int* in_sizes, int n_in,
                              void* d_out, int out_size) {
    const float* vs    = (const float*)d_in[0];
    const int*   edges = (const int*)d_in[1];
    const int*   bidx  = (const int*)d_in[2];
    int wb = n_in - 13;
    const float* Ws0 = (const float*)d_in[wb + 0];
    const float* Wn0 = (const float*)d_in[wb + 1];
    const float* b0  = (const float*)d_in[wb + 2];
    const float* Ws1 = (const float*)d_in[wb + 3];
    const float* Wn1 = (const float*)d_in[wb + 4];
    const float* b1  = (const float*)d_in[wb + 5];
    const float* Ws2 = (const float*)d_in[wb + 6];
    const float* Wn2 = (const float*)d_in[wb + 7];
    const float* b2  = (const float*)d_in[wb + 8];
    const float* Wd  = (const float*)d_in[wb + 9];
    const float* bd  = (const float*)d_in[wb + 10];
    const float* Wo  = (const float*)d_in[wb + 11];
    const float* bo  = (const float*)d_in[wb + 12];
    float* out = (float*)d_out;

    cudaFuncSetAttribute(k_node1, cudaFuncAttributeMaxDynamicSharedMemorySize, 65536);
    cudaFuncSetAttribute(k_node2, cudaFuncAttributeMaxDynamicSharedMemorySize, 131072);

    k_init<<<512, 256>>>();                          // covers max(NN, NB*128)
    k_markB<<<1, 256>>>(vs, bidx);
    k_pass1<<<(NE + 255) / 256, 256>>>(vs, edges);   // agg0 atomics + N1 mark + e2 emit
    k_pass2<<<(NE + 255) / 256, 256>>>(edges);       // N2 mark + e1 emit
    k_compact<<<(NN + 255) / 256, 256>>>();
    k_zero_agg1<<<GSB, 256>>>();
    k_node0<<<GSB, 256>>>(vs, Ws0, Wn0, b0);
    k_edge1<<<GSB, 256>>>();
    k_node1<<<148, 128, 65536>>>(Ws1, Wn1, b1);
    k_edge2<<<296, 256>>>();
    k_node2<<<128, 128, 131072>>>(bidx, Ws2, Wn2, b2);
    k_final<<<1, 256>>>(Wd, bd, Wo, bo, out);
}

// round 4
// speedup vs baseline: 1.6630x; 1.1468x over previous
#include <cuda_runtime.h>

#define NN 100000
#define NE 300000
#define NB 1024
#define GSB 1184          // grid blocks for dynamic-work (grid-stride) kernels

// ---------------- device scratch (static, 16B-aligned via float4) ----------------
__device__ float4 g_agg0[NN];             // position agg, padded to 4 floats/node
__device__ float4 g_agg1[NN * 16];        // layer1 agg, compact by slot1 (cnt1*16 used)
__device__ float4 g_agg2[NB * 32];        // layer2 agg, compact by slot2
__device__ float4 g_x1[NN * 16];          // layer0 out (written only at N2 nodes)
__device__ float4 g_x2c[NN * 32];         // layer1 out, compact by slot1
__device__ unsigned char g_maskB[NN];
__device__ unsigned char g_maskN1[NN];
__device__ unsigned char g_maskN2[NN];
__device__ int g_slot1[NN];
__device__ int g_slot2[NN];
__device__ int g_list1[NN];               // slot1 -> node
__device__ int g_list2[NN];               // N2 node list
__device__ int2 g_e1[NE];                 // active layer1 edges (packed)
__device__ int2 g_e2[NE];                 // active layer2 edges (packed)
__device__ int g_cnt1, g_cnt2, g_cntE1, g_cntE2;
__device__ float g_pool[256];
__device__ float g_bsum[3];

// ---------------- init ----------------
__global__ void k_init() {
    int i = blockIdx.x * 256 + threadIdx.x;
    float4 z = make_float4(0.f, 0.f, 0.f, 0.f);
    if (i < NN) {
        g_maskB[i] = 0; g_maskN1[i] = 0; g_maskN2[i] = 0;
        g_agg0[i] = z;
    }
    if (i < NB * 32) g_agg2[i] = z;
    if (i < 256) g_pool[i] = 0.f;
    if (i < 3) g_bsum[i] = 0.f;
    if (i == 0) { g_cnt1 = 0; g_cnt2 = 0; g_cntE1 = 0; g_cntE2 = 0; }
}

// ---------------- mark boundary + boundary mean of vs ----------------
__global__ void k_markB(const float* __restrict__ vs, const int* __restrict__ bidx) {
    int tid = threadIdx.x;
    float s0 = 0.f, s1 = 0.f, s2 = 0.f;
    for (int j = tid; j < NB; j += 256) {
        int n = bidx[j];
        g_maskB[n] = 1; g_maskN1[n] = 1; g_slot2[n] = j;
        s0 += vs[3 * n]; s1 += vs[3 * n + 1]; s2 += vs[3 * n + 2];
    }
    atomicAdd(&g_bsum[0], s0);
    atomicAdd(&g_bsum[1], s1);
    atomicAdd(&g_bsum[2], s2);
}

// ---------------- pass 1: position agg (vector red) + N1 mark + e2 emit; 2 edges/thread ----------------
__global__ void k_pass1(const float* __restrict__ vs, const int* __restrict__ edges) {
    int i = blockIdx.x * 256 + threadIdx.x;
    if (i >= NE / 2) return;
    int4 ed = ((const int4*)edges)[i];
    int s0 = ed.x, d0 = ed.y, s1 = ed.z, d1 = ed.w;
    // gather positions (12 independent loads -> high MLP)
    float ax = vs[3 * s0], ay = vs[3 * s0 + 1], az = vs[3 * s0 + 2];
    float bx = vs[3 * d0], by = vs[3 * d0 + 1], bz = vs[3 * d0 + 2];
    float cx = vs[3 * s1], cy = vs[3 * s1 + 1], cz = vs[3 * s1 + 2];
    float ex = vs[3 * d1], ey = vs[3 * d1 + 1], ez = vs[3 * d1 + 2];
    atomicAdd(&g_agg0[d0], make_float4(ax, ay, az, 0.f));
    atomicAdd(&g_agg0[s0], make_float4(bx, by, bz, 0.f));
    atomicAdd(&g_agg0[d1], make_float4(cx, cy, cz, 0.f));
    atomicAdd(&g_agg0[s1], make_float4(ex, ey, ez, 0.f));
    int bs0 = g_maskB[s0], bd0 = g_maskB[d0];
    int bs1 = g_maskB[s1], bd1 = g_maskB[d1];
    int a0 = (bs0 | bd0), a1 = (bs1 | bd1);
    if (a0 | a1) {
        if (bd0) g_maskN1[s0] = 1;
        if (bs0) g_maskN1[d0] = 1;
        if (bd1) g_maskN1[s1] = 1;
        if (bs1) g_maskN1[d1] = 1;
        int p = atomicAdd(&g_cntE2, a0 + a1);
        if (a0) g_e2[p++] = make_int2(s0 | (bs0 << 30), d0 | (bd0 << 30));
        if (a1) g_e2[p]   = make_int2(s1 | (bs1 << 30), d1 | (bd1 << 30));
    }
}

// ---------------- pass 2: N2 mark + e1 emit; 2 edges/thread ----------------
__global__ void k_pass2(const int* __restrict__ edges) {
    int i = blockIdx.x * 256 + threadIdx.x;
    if (i >= NE / 2) return;
    int4 ed = ((const int4*)edges)[i];
    int s0 = ed.x, d0 = ed.y, s1 = ed.z, d1 = ed.w;
    int as0 = g_maskN1[s0], ad0 = g_maskN1[d0];
    int as1 = g_maskN1[s1], ad1 = g_maskN1[d1];
    int a0 = (as0 | ad0), a1 = (as1 | ad1);
    if (a0 | a1) {
        if (ad0) g_maskN2[s0] = 1;
        if (as0) g_maskN2[d0] = 1;
        if (ad1) g_maskN2[s1] = 1;
        if (as1) g_maskN2[d1] = 1;
        int p = atomicAdd(&g_cntE1, a0 + a1);
        if (a0) g_e1[p++] = make_int2(s0 | (as0 << 30), d0 | (ad0 << 30));
        if (a1) g_e1[p]   = make_int2(s1 | (as1 << 30), d1 | (ad1 << 30));
    }
}

// ---------------- compaction (+ zero agg1 row for each new slot) ----------------
__global__ void k_compact() {
    int i = blockIdx.x * 256 + threadIdx.x;
    if (i >= NN) return;
    int n1 = g_maskN1[i];
    if (n1) {
        int p = atomicAdd(&g_cnt1, 1);
        g_slot1[i] = p; g_list1[p] = i;
        float4 z = make_float4(0.f, 0.f, 0.f, 0.f);
#pragma unroll
        for (int c = 0; c < 16; c++) g_agg1[p * 16 + c] = z;
    }
    if (n1 | g_maskN2[i]) { int p = atomicAdd(&g_cnt2, 1); g_list2[p] = i; }
}

// ---------------- layer 0 node update (N2 nodes only) ----------------
__global__ void k_node0(const float* __restrict__ vs,
                        const float* __restrict__ Ws, const float* __restrict__ Wn,
                        const float* __restrict__ b) {
    int tot = g_cnt2 << 6;
    int stride = gridDim.x * blockDim.x;
    for (int t = blockIdx.x * blockDim.x + threadIdx.x; t < tot; t += stride) {
        int ni = t >> 6, c = t & 63;
        int node = g_list2[ni];
        float4 a = g_agg0[node];
        float acc = b[c]
            + vs[3 * node] * Ws[c] + vs[3 * node + 1] * Ws[64 + c] + vs[3 * node + 2] * Ws[128 + c]
            + a.x * Wn[c] + a.y * Wn[64 + c] + a.z * Wn[128 + c];
        ((float*)g_x1)[node * 64 + c] = fmaxf(acc, 0.f);
    }
}

// ---------------- layer 1 edge aggregation: 16 threads/edge, 1 vector atomic/dir ----------------
__global__ void k_edge1() {
    int tot = g_cntE1 << 4;
    int stride = gridDim.x * blockDim.x;
    for (int t = blockIdx.x * blockDim.x + threadIdx.x; t < tot; t += stride) {
        int ei = t >> 4, c4 = t & 15;
        int2 en = g_e1[ei];
        int s = en.x & 0x3FFFFFFF, sa = (unsigned)en.x >> 30;
        int d = en.y & 0x3FFFFFFF, da = (unsigned)en.y >> 30;
        if (da) atomicAdd(&g_agg1[g_slot1[d] * 16 + c4], g_x1[s * 16 + c4]);
        if (sa) atomicAdd(&g_agg1[g_slot1[s] * 16 + c4], g_x1[d * 16 + c4]);
    }
}

// ---------------- layer 1 node update: 256 threads, 2 slots/iter ----------------
__global__ void k_node1(const float* __restrict__ Ws, const float* __restrict__ Wn,
                        const float* __restrict__ b) {
    extern __shared__ float sm[];
    float* sWs = sm;            // 64*128
    float* sWn = sm + 8192;
    __shared__ float xs[2][64], as[2][64];
    int tid = threadIdx.x;
    int pair = tid >> 7, c = tid & 127;
    for (int i = tid; i < 8192; i += 256) { sWs[i] = Ws[i]; sWn[i] = Wn[i]; }
    float bc = b[c];
    __syncthreads();
    int cnt = g_cnt1;
    for (int slot0 = blockIdx.x * 2; slot0 < cnt; slot0 += gridDim.x * 2) {
        int slot = slot0 + pair;
        bool act = slot < cnt;
        if (act && c < 128) {
            int node = g_list1[slot];
            if (c < 64) xs[pair][c] = ((const float*)g_x1)[node * 64 + c];
            else        as[pair][c - 64] = ((const float*)g_agg1)[slot * 64 + (c - 64)];
        }
        __syncthreads();
        if (act) {
            float acc = bc;
#pragma unroll 16
            for (int k = 0; k < 64; k++)
                acc += xs[pair][k] * sWs[k * 128 + c] + as[pair][k] * sWn[k * 128 + c];
            ((float*)g_x2c)[slot * 128 + c] = fmaxf(acc, 0.f);
        }
        __syncthreads();
    }
}

// ---------------- layer 2 edge aggregation: 32 threads/edge, 1 vector atomic/dir ----------------
__global__ void k_edge2() {
    int tot = g_cntE2 << 5;
    int stride = gridDim.x * blockDim.x;
    for (int t = blockIdx.x * blockDim.x + threadIdx.x; t < tot; t += stride) {
        int ei = t >> 5, c4 = t & 31;
        int2 en = g_e2[ei];
        int s = en.x & 0x3FFFFFFF, bs = (unsigned)en.x >> 30;
        int d = en.y & 0x3FFFFFFF, bd = (unsigned)en.y >> 30;
        if (bd) atomicAdd(&g_agg2[g_slot2[d] * 32 + c4], g_x2c[g_slot1[s] * 32 + c4]);
        if (bs) atomicAdd(&g_agg2[g_slot2[s] * 32 + c4], g_x2c[g_slot1[d] * 32 + c4]);
    }
}

// ---------------- layer 2 node update + pooling: 256 threads, 2 entry-groups ----------------
// 128 blocks: blockIdx = g*2+h (h = cout half). Each block: 16 boundary entries,
// threads split into 2 halves of 128, each half does 8 entries.
__global__ void k_node2(const int* __restrict__ bidx,
                        const float* __restrict__ Ws, const float* __restrict__ Wn,
                        const float* __restrict__ b) {
    extern __shared__ float sm[];
    float* sWs = sm;            // 128*128 for this cout half
    float* sWn = sm + 16384;
    __shared__ float xs[2][128], as[2][128];
    int tid = threadIdx.x;
    int eh = tid >> 7, c = tid & 127;
    int h = blockIdx.x & 1, g = blockIdx.x >> 1;
    for (int i = tid; i < 16384; i += 256) {
        int k = i >> 7, cc = i & 127;
        sWs[i] = Ws[k * 256 + h * 128 + cc];
        sWn[i] = Wn[k * 256 + h * 128 + cc];
    }
    float bb = b[h * 128 + c];
    __syncthreads();
    float pacc = 0.f;
    for (int e = 0; e < 8; e++) {
        int node = bidx[g * 16 + eh * 8 + e];
        xs[eh][c] = ((const float*)g_x2c)[g_slot1[node] * 128 + c];
        as[eh][c] = ((const float*)g_agg2)[g_slot2[node] * 128 + c];
        __syncthreads();
        float acc = bb;
#pragma unroll 16
        for (int k = 0; k < 128; k++)
            acc += xs[eh][k] * sWs[k * 128 + c] + as[eh][k] * sWn[k * 128 + c];
        pacc += fmaxf(acc, 0.f);
        __syncthreads();
    }
    atomicAdd(&g_pool[h * 128 + c], pacc);
}

// ---------------- dense head ----------------
__global__ void k_final(const float* __restrict__ Wd, const float* __restrict__ bd,
                        const float* __restrict__ Wo, const float* __restrict__ bo,
                        float* __restrict__ out) {
    __shared__ float sp[256], sh[256];
    int tid = threadIdx.x;
    sp[tid] = g_pool[tid] * (1.f / NB);
    __syncthreads();
    float acc = bd[tid];
#pragma unroll 8
    for (int k = 0; k < 256; k++) acc += sp[k] * Wd[k * 256 + tid];
    sh[tid] = fmaxf(acc, 0.f);
    __syncthreads();
    if (tid < 12) {
        float o = bo[tid];
        for (int k = 0; k < 256; k++) o += sh[k] * Wo[k * 12 + tid];
        out[tid] = o + g_bsum[tid % 3] * (1.f / NB);
    }
}

// ---------------- host launch ----------------
extern "C" void kernel_launch(void* const* d_in, const int* in_sizes, int n_in,
                              void* d_out, int out_size) {
    const float* vs    = (const float*)d_in[0];
    const int*   edges = (const int*)d_in[1];
    const int*   bidx  = (const int*)d_in[2];
    int wb = n_in - 13;
    const float* Ws0 = (const float*)d_in[wb + 0];
    const float* Wn0 = (const float*)d_in[wb + 1];
    const float* b0  = (const float*)d_in[wb + 2];
    const float* Ws1 = (const float*)d_in[wb + 3];
    const float* Wn1 = (const float*)d_in[wb + 4];
    const float* b1  = (const float*)d_in[wb + 5];
    const float* Ws2 = (const float*)d_in[wb + 6];
    const float* Wn2 = (const float*)d_in[wb + 7];
    const float* b2  = (const float*)d_in[wb + 8];
    const float* Wd  = (const float*)d_in[wb + 9];
    const float* bd  = (const float*)d_in[wb + 10];
    const float* Wo  = (const float*)d_in[wb + 11];
    const float* bo  = (const float*)d_in[wb + 12];
    float* out = (float*)d_out;

    cudaFuncSetAttribute(k_node1, cudaFuncAttributeMaxDynamicSharedMemorySize, 65536);
    cudaFuncSetAttribute(k_node2, cudaFuncAttributeMaxDynamicSharedMemorySize, 131072);

    k_init<<<(NN + 255) / 256, 256>>>();
    k_markB<<<1, 256>>>(vs, bidx);
    k_pass1<<<(NE / 2 + 255) / 256, 256>>>(vs, edges);
    k_pass2<<<(NE / 2 + 255) / 256, 256>>>(edges);
    k_compact<<<(NN + 255) / 256, 256>>>();
    k_node0<<<GSB, 256>>>(vs, Ws0, Wn0, b0);
    k_edge1<<<GSB, 256>>>();
    k_node1<<<148, 256, 65536>>>(Ws1, Wn1, b1);
    k_edge2<<<592, 256>>>();
    k_node2<<<128, 256, 131072>>>(bidx, Ws2, Wn2, b2);
    k_final<<<1, 256>>>(Wd, bd, Wo, bo, out);
}

// round 5
// speedup vs baseline: 2.0601x; 1.2388x over previous
#include <cuda_runtime.h>

#define NN 100000
#define NE 300000
#define NB 1024
#define GSB 1184          // grid blocks for dynamic-work (grid-stride) kernels

// ---------------- device scratch (static, 16B-aligned via float4) ----------------
__device__ float4 g_agg0[NN];             // position agg, padded to 4 floats/node
__device__ float4 g_agg1[NN * 16];        // layer1 agg, compact by slot1 (cnt1*16 used)
__device__ float4 g_agg2[NB * 32];        // layer2 agg, compact by slot2
__device__ float4 g_x1[NN * 16];          // layer0 out (written only at N2 nodes)
__device__ float4 g_x2c[NN * 32];         // layer1 out, compact by slot1
__device__ unsigned char g_maskB[NN];
__device__ unsigned char g_maskN1[NN];
__device__ unsigned char g_maskN2[NN];
__device__ int g_slot1[NN];
__device__ int g_slot2[NN];
__device__ int g_list1[NN];               // slot1 -> node
__device__ int g_list2[NN];               // N2 node list
__device__ int2 g_e1[NE];                 // active layer1 edges (packed)
__device__ int2 g_e2[NE];                 // active layer2 edges (packed)
__device__ int g_cnt1, g_cnt2, g_cntE1, g_cntE2;
__device__ float g_pool[256];
__device__ float g_bsum[3];

// ---------------- init ----------------
__global__ void k_init() {
    int i = blockIdx.x * 256 + threadIdx.x;
    float4 z = make_float4(0.f, 0.f, 0.f, 0.f);
    if (i < NN) {
        g_maskB[i] = 0; g_maskN1[i] = 0; g_maskN2[i] = 0;
        g_agg0[i] = z;
    }
    if (i < NB * 32) g_agg2[i] = z;
    if (i < 256) g_pool[i] = 0.f;
    if (i < 3) g_bsum[i] = 0.f;
    if (i == 0) { g_cnt1 = 0; g_cnt2 = 0; g_cntE1 = 0; g_cntE2 = 0; }
}

// ---------------- mark boundary + boundary mean of vs ----------------
__global__ void k_markB(const float* __restrict__ vs, const int* __restrict__ bidx) {
    int tid = threadIdx.x;
    float s0 = 0.f, s1 = 0.f, s2 = 0.f;
    for (int j = tid; j < NB; j += 256) {
        int n = bidx[j];
        g_maskB[n] = 1; g_maskN1[n] = 1; g_slot2[n] = j;
        s0 += vs[3 * n]; s1 += vs[3 * n + 1]; s2 += vs[3 * n + 2];
    }
    atomicAdd(&g_bsum[0], s0);
    atomicAdd(&g_bsum[1], s1);
    atomicAdd(&g_bsum[2], s2);
}

// ---------------- pass 1: position agg (vector red) + N1 mark + e2 emit; 1 edge/thread ----------------
__global__ void k_pass1(const float* __restrict__ vs, const int* __restrict__ edges) {
    int e = blockIdx.x * 256 + threadIdx.x;
    if (e >= NE) return;
    int s = edges[2 * e], d = edges[2 * e + 1];
    float sx = vs[3 * s], sy = vs[3 * s + 1], sz = vs[3 * s + 2];
    float dx = vs[3 * d], dy = vs[3 * d + 1], dz = vs[3 * d + 2];
    atomicAdd(&g_agg0[d], make_float4(sx, sy, sz, 0.f));
    atomicAdd(&g_agg0[s], make_float4(dx, dy, dz, 0.f));
    int bs = g_maskB[s], bd = g_maskB[d];
    if (bs | bd) {
        if (bd) g_maskN1[s] = 1;
        if (bs) g_maskN1[d] = 1;
        int p = atomicAdd(&g_cntE2, 1);
        g_e2[p] = make_int2(s | (bs << 30), d | (bd << 30));
    }
}

// ---------------- pass 2: N2 mark + e1 emit; 1 edge/thread ----------------
__global__ void k_pass2(const int* __restrict__ edges) {
    int e = blockIdx.x * 256 + threadIdx.x;
    if (e >= NE) return;
    int s = edges[2 * e], d = edges[2 * e + 1];
    int as = g_maskN1[s], ad = g_maskN1[d];
    if (as | ad) {
        if (ad) g_maskN2[s] = 1;     // need x1[s]
        if (as) g_maskN2[d] = 1;     // need x1[d]
        int p = atomicAdd(&g_cntE1, 1);
        g_e1[p] = make_int2(s | (as << 30), d | (ad << 30));
    }
}

// ---------------- compaction (+ zero agg1 row for each new slot) ----------------
__global__ void k_compact() {
    int i = blockIdx.x * 256 + threadIdx.x;
    if (i >= NN) return;
    int n1 = g_maskN1[i];
    if (n1) {
        int p = atomicAdd(&g_cnt1, 1);
        g_slot1[i] = p; g_list1[p] = i;
        float4 z = make_float4(0.f, 0.f, 0.f, 0.f);
#pragma unroll
        for (int c = 0; c < 16; c++) g_agg1[p * 16 + c] = z;
    }
    if (n1 | g_maskN2[i]) { int p = atomicAdd(&g_cnt2, 1); g_list2[p] = i; }
}

// ---------------- layer 0 node update (N2 nodes only) ----------------
__global__ void k_node0(const float* __restrict__ vs,
                        const float* __restrict__ Ws, const float* __restrict__ Wn,
                        const float* __restrict__ b) {
    int tot = g_cnt2 << 6;
    int stride = gridDim.x * blockDim.x;
    for (int t = blockIdx.x * blockDim.x + threadIdx.x; t < tot; t += stride) {
        int ni = t >> 6, c = t & 63;
        int node = g_list2[ni];
        float4 a = g_agg0[node];
        float acc = b[c]
            + vs[3 * node] * Ws[c] + vs[3 * node + 1] * Ws[64 + c] + vs[3 * node + 2] * Ws[128 + c]
            + a.x * Wn[c] + a.y * Wn[64 + c] + a.z * Wn[128 + c];
        ((float*)g_x1)[node * 64 + c] = fmaxf(acc, 0.f);
    }
}

// ---------------- layer 1 edge aggregation: 16 threads/edge, 1 vector atomic/dir ----------------
__global__ void k_edge1() {
    int tot = g_cntE1 << 4;
    int stride = gridDim.x * blockDim.x;
    for (int t = blockIdx.x * blockDim.x + threadIdx.x; t < tot; t += stride) {
        int ei = t >> 4, c4 = t & 15;
        int2 en = g_e1[ei];
        int s = en.x & 0x3FFFFFFF, sa = (unsigned)en.x >> 30;
        int d = en.y & 0x3FFFFFFF, da = (unsigned)en.y >> 30;
        if (da) atomicAdd(&g_agg1[g_slot1[d] * 16 + c4], g_x1[s * 16 + c4]);
        if (sa) atomicAdd(&g_agg1[g_slot1[s] * 16 + c4], g_x1[d * 16 + c4]);
    }
}

// ---------------- layer 1 node update: 256 threads, 2 slots/iter ----------------
__global__ void k_node1(const float* __restrict__ Ws, const float* __restrict__ Wn,
                        const float* __restrict__ b) {
    extern __shared__ float sm[];
    float* sWs = sm;            // 64*128
    float* sWn = sm + 8192;
    __shared__ float xs[2][64], as[2][64];
    int tid = threadIdx.x;
    int pair = tid >> 7, c = tid & 127;
    for (int i = tid; i < 8192; i += 256) { sWs[i] = Ws[i]; sWn[i] = Wn[i]; }
    float bc = b[c];
    __syncthreads();
    int cnt = g_cnt1;
    for (int slot0 = blockIdx.x * 2; slot0 < cnt; slot0 += gridDim.x * 2) {
        int slot = slot0 + pair;
        bool act = slot < cnt;
        if (act && c < 128) {
            int node = g_list1[slot];
            if (c < 64) xs[pair][c] = ((const float*)g_x1)[node * 64 + c];
            else        as[pair][c - 64] = ((const float*)g_agg1)[slot * 64 + (c - 64)];
        }
        __syncthreads();
        if (act) {
            float acc = bc;
#pragma unroll 16
            for (int k = 0; k < 64; k++)
                acc += xs[pair][k] * sWs[k * 128 + c] + as[pair][k] * sWn[k * 128 + c];
            ((float*)g_x2c)[slot * 128 + c] = fmaxf(acc, 0.f);
        }
        __syncthreads();
    }
}

// ---------------- layer 2 edge aggregation: 32 threads/edge, 1 vector atomic/dir ----------------
__global__ void k_edge2() {
    int tot = g_cntE2 << 5;
    int stride = gridDim.x * blockDim.x;
    for (int t = blockIdx.x * blockDim.x + threadIdx.x; t < tot; t += stride) {
        int ei = t >> 5, c4 = t & 31;
        int2 en = g_e2[ei];
        int s = en.x & 0x3FFFFFFF, bs = (unsigned)en.x >> 30;
        int d = en.y & 0x3FFFFFFF, bd = (unsigned)en.y >> 30;
        if (bd) atomicAdd(&g_agg2[g_slot2[d] * 32 + c4], g_x2c[g_slot1[s] * 32 + c4]);
        if (bs) atomicAdd(&g_agg2[g_slot2[s] * 32 + c4], g_x2c[g_slot1[d] * 32 + c4]);
    }
}

// ---------------- layer 2 node update + pooling: 256 threads, 2 entry-groups ----------------
// 128 blocks: blockIdx = g*2+h (h = cout half). Each block: 16 boundary entries,
// threads split into 2 halves of 128, each half does 8 entries.
__global__ void k_node2(const int* __restrict__ bidx,
                        const float* __restrict__ Ws, const float* __restrict__ Wn,
                        const float* __restrict__ b) {
    extern __shared__ float sm[];
    float* sWs = sm;            // 128*128 for this cout half
    float* sWn = sm + 16384;
    __shared__ float xs[2][128], as[2][128];
    int tid = threadIdx.x;
    int eh = tid >> 7, c = tid & 127;
    int h = blockIdx.x & 1, g = blockIdx.x >> 1;
    for (int i = tid; i < 16384; i += 256) {
        int k = i >> 7, cc = i & 127;
        sWs[i] = Ws[k * 256 + h * 128 + cc];
        sWn[i] = Wn[k * 256 + h * 128 + cc];
    }
    float bb = b[h * 128 + c];
    __syncthreads();
    float pacc = 0.f;
    for (int e = 0; e < 8; e++) {
        int node = bidx[g * 16 + eh * 8 + e];
        xs[eh][c] = ((const float*)g_x2c)[g_slot1[node] * 128 + c];
        as[eh][c] = ((const float*)g_agg2)[g_slot2[node] * 128 + c];
        __syncthreads();
        float acc = bb;
#pragma unroll 16
        for (int k = 0; k < 128; k++)
            acc += xs[eh][k] * sWs[k * 128 + c] + as[eh][k] * sWn[k * 128 + c];
        pacc += fmaxf(acc, 0.f);
        __syncthreads();
    }
    atomicAdd(&g_pool[h * 128 + c], pacc);
}

// ---------------- dense head ----------------
__global__ void k_final(const float* __restrict__ Wd, const float* __restrict__ bd,
                        const float* __restrict__ Wo, const float* __restrict__ bo,
                        float* __restrict__ out) {
    __shared__ float sp[256], sh[256];
    int tid = threadIdx.x;
    sp[tid] = g_pool[tid] * (1.f / NB);
    __syncthreads();
    float acc = bd[tid];
#pragma unroll 8
    for (int k = 0; k < 256; k++) acc += sp[k] * Wd[k * 256 + tid];
    sh[tid] = fmaxf(acc, 0.f);
    __syncthreads();
    if (tid < 12) {
        float o = bo[tid];
        for (int k = 0; k < 256; k++) o += sh[k] * Wo[k * 12 + tid];
        out[tid] = o + g_bsum[tid % 3] * (1.f / NB);
    }
}

// ---------------- host launch ----------------
extern "C" void kernel_launch(void* const* d_in, const int* in_sizes, int n_in,
                              void* d_out, int out_size) {
    const float* vs    = (const float*)d_in[0];
    const int*   edges = (const int*)d_in[1];
    const int*   bidx  = (const int*)d_in[2];
    int wb = n_in - 13;
    const float* Ws0 = (const float*)d_in[wb + 0];
    const float* Wn0 = (const float*)d_in[wb + 1];
    const float* b0  = (const float*)d_in[wb + 2];
    const float* Ws1 = (const float*)d_in[wb + 3];
    const float* Wn1 = (const float*)d_in[wb + 4];
    const float* b1  = (const float*)d_in[wb + 5];
    const float* Ws2 = (const float*)d_in[wb + 6];
    const float* Wn2 = (const float*)d_in[wb + 7];
    const float* b2  = (const float*)d_in[wb + 8];
    const float* Wd  = (const float*)d_in[wb + 9];
    const float* bd  = (const float*)d_in[wb + 10];
    const float* Wo  = (const float*)d_in[wb + 11];
    const float* bo  = (const float*)d_in[wb + 12];
    float* out = (float*)d_out;

    cudaFuncSetAttribute(k_node1, cudaFuncAttributeMaxDynamicSharedMemorySize, 65536);
    cudaFuncSetAttribute(k_node2, cudaFuncAttributeMaxDynamicSharedMemorySize, 131072);

    k_init<<<(NN + 255) / 256, 256>>>();
    k_markB<<<1, 256>>>(vs, bidx);
    k_pass1<<<(NE + 255) / 256, 256>>>(vs, edges);
    k_pass2<<<(NE + 255) / 256, 256>>>(edges);
    k_compact<<<(NN + 255) / 256, 256>>>();
    k_node0<<<GSB, 256>>>(vs, Ws0, Wn0, b0);
    k_edge1<<<GSB, 256>>>();
    k_node1<<<296, 256, 65536>>>(Ws1, Wn1, b1);
    k_edge2<<<592, 256>>>();
    k_node2<<<128, 256, 131072>>>(bidx, Ws2, Wn2, b2);
    k_final<<<1, 256>>>(Wd, bd, Wo, bo, out);
}